// round 17
// baseline (speedup 1.0000x reference)
#include <cuda_runtime.h>
#include <cuda.h>
#include <dlfcn.h>
#include <cstdint>
#include <math.h>

#define B_DIM 16384
#define I_DIM 1024
#define H_DIM 1024

#if defined(__CUDA_ARCH__) && (defined(__CUDA_ARCH_FEAT_SM103_ALL) || defined(__CUDA_ARCH_FEAT_SM100_ALL))
#define HAVE_TCGEN05 1
#else
#define HAVE_TCGEN05 0
#endif

__device__ __forceinline__ uint32_t smem_u32(const void* p) {
    uint32_t a;
    asm("{ .reg .u64 t; cvta.to.shared.u64 t, %1; cvt.u32.u64 %0, t; }" : "=r"(a) : "l"(p));
    return a;
}

// ===========================================================================
// tcgen05 cg2 tf32 GRU — round-16 kernel with ONE pipeline restructure:
// ring deepened to NST=5 independent stages with per-stage EMPTY + per-stage
// commit (producer runs up to 4 stages ahead; ~3072 cyc prefetch cushion vs
// the ~1200 cyc TMA refill chain that was starving the tensor pipe at 44%).
// ===========================================================================
#if HAVE_TCGEN05

#define MBAR_INIT(addr, cnt) \
    asm volatile("mbarrier.init.shared.b64 [%0], %1;" :: "r"(addr), "r"(cnt) : "memory")
#define MBAR_EXPECT_TX(addr, bytes) \
    asm volatile("mbarrier.arrive.expect_tx.shared.b64 _, [%0], %1;" \
                 :: "r"(addr), "r"(bytes) : "memory")
#define MBAR_WAIT(addr, ph) do {                                                   \
    uint32_t _m = (addr); uint32_t _p = (ph); uint32_t _done;                      \
    asm volatile("{\n\t.reg .pred p;\n\t"                                          \
        "mbarrier.try_wait.parity.acquire.cta.shared::cta.b64 p, [%1], %2;\n\t"    \
        "selp.b32 %0, 1, 0, p;\n\t}"                                               \
        : "=r"(_done) : "r"(_m), "r"(_p) : "memory");                              \
    if (!_done) {                                                                  \
        asm volatile("{\n\t.reg .pred P1;\n\t"                                     \
            "WL_%=:\n\t"                                                           \
            "mbarrier.try_wait.parity.acquire.cta.shared::cta.b64 P1, [%0], %1, 0x989680;\n\t" \
            "@P1 bra.uni WD_%=;\n\t"                                               \
            "bra.uni WL_%=;\n\t"                                                   \
            "WD_%=:\n\t}"                                                          \
            :: "r"(_m), "r"(_p) : "memory");                                       \
    }                                                                              \
} while (0)

// cta_group::2 3D TMA: data -> local CTA smem; complete_tx -> LEADER CTA's
// barrier (bit 24 cleared). Both CTAs of the pair execute this.
#define TMA_3D_CG2(smem_addr, map, cx, cy, cz, mbar) \
    asm volatile("{\n\t.reg .b32 lb;\n\t" \
                 "and.b32 lb, %5, 0xFEFFFFFF;\n\t" \
                 "cp.async.bulk.tensor.3d.cta_group::2.shared::cluster.global" \
                 ".tile.mbarrier::complete_tx::bytes " \
                 "[%0], [%1, {%2, %3, %4}], [lb];\n\t}" \
                 :: "r"(smem_addr), "l"(map), "r"(cx), "r"(cy), "r"(cz), \
                    "r"(mbar) : "memory")

#define ALLOC_CG2(res, n) \
    asm volatile("tcgen05.alloc.cta_group::2.sync.aligned.shared::cta.b32 [%0], %1;" :: "r"(res), "r"(n) : "memory")
#define DEALLOC_CG2(t, n) \
    asm volatile("tcgen05.dealloc.cta_group::2.sync.aligned.b32 %0, %1;" :: "r"(t), "r"(n))
#define RELINQ_CG2() \
    asm volatile("tcgen05.relinquish_alloc_permit.cta_group::2.sync.aligned;")
#define COMMIT_MC(addr) \
    asm volatile("tcgen05.commit.cta_group::2.mbarrier::arrive::one.shared::cluster.multicast::cluster.b64 [%0], %1;" \
                 :: "r"(addr), "h"((uint16_t)3) : "memory")
#define TC_FENCE_BEFORE() asm volatile("tcgen05.fence::before_thread_sync;" ::: "memory")
#define TC_FENCE_AFTER()  asm volatile("tcgen05.fence::after_thread_sync;" ::: "memory")
#define TC_WAIT_LD()      asm volatile("tcgen05.wait::ld.sync.aligned;" ::: "memory")
#define CLUSTER_SYNC_() do { \
    asm volatile("barrier.cluster.arrive.aligned;" ::: "memory"); \
    asm volatile("barrier.cluster.wait.aligned;" ::: "memory"); } while (0)

#define LD_X16(r, a) \
    asm volatile("tcgen05.ld.sync.aligned.32x32b.x16.b32 " \
        "{%0, %1, %2, %3, %4, %5, %6, %7, %8, %9, %10, %11, %12, %13, %14, %15}, [%16];" \
        : "=r"((r)[0]), "=r"((r)[1]), "=r"((r)[2]), "=r"((r)[3]), \
          "=r"((r)[4]), "=r"((r)[5]), "=r"((r)[6]), "=r"((r)[7]), \
          "=r"((r)[8]), "=r"((r)[9]), "=r"((r)[10]), "=r"((r)[11]), \
          "=r"((r)[12]), "=r"((r)[13]), "=r"((r)[14]), "=r"((r)[15]) \
        : "r"(a))

__device__ __forceinline__ void mma_tf32_cg2(uint32_t d, uint64_t ad, uint64_t bd,
                                             uint32_t idesc, uint32_t en) {
    asm volatile(
        "{\n\t.reg .pred p;\n\tsetp.ne.u32 p, %4, 0;\n\t"
        "tcgen05.mma.cta_group::2.kind::tf32 [%0], %1, %2, %3, "
        "{%5, %5, %5, %5, %5, %5, %5, %5}, p;\n\t}"
        :: "r"(d), "l"(ad), "l"(bd), "r"(idesc), "r"(en), "r"(0u)
        : "memory");
}

__device__ __forceinline__ uint64_t sdesc(uint32_t addr) {
    return ((uint64_t)2 << 61) | ((uint64_t)1 << 46) | ((uint64_t)64 << 32) |
           ((uint64_t)1 << 16) | ((addr >> 4) & 0x3FFF);
}

#endif // HAVE_TCGEN05

constexpr int NST = 5;                 // 5 independent 40KB stages
constexpr int STAGE_BYTES = 40960;     // A 16KB + 3x B 8KB
constexpr int SMEM_STAGE0 = 4096;
constexpr int SMEM_TOTAL_TC = SMEM_STAGE0 + NST * STAGE_BYTES;   // 208896

// idesc: dtype=f32(1)<<4, atype=tf32(2)<<7, btype=tf32(2)<<10, N/8<<17, M/16<<24
constexpr uint32_t IDESC_TF32 = (1u << 4) | (2u << 7) | (2u << 10) | (16u << 17) | (16u << 24);

constexpr int OFF_TMEM  = 0;
constexpr int OFF_FULL  = 16;    // 5 x 8B  (per stage; rank0, expect_tx both CTAs)
constexpr int OFF_EMPTY = 56;    // 5 x 8B  (per stage; multicast commit)
constexpr int OFF_DONE  = 96;
constexpr int OFF_BIAS  = 128;   // 512 floats

constexpr uint32_t STAGE_TX2 = 2 * 40960;   // both CTAs' bytes per stage

// De-bias for double RZ tf32 truncation (both operands raw).
#define TRUNC_DEBIAS 1.000677f

__global__ void __launch_bounds__(288, 1) __cluster_dims__(2, 1, 1)
gru_tc_kernel(const __grid_constant__ CUtensorMap mapX,
              const __grid_constant__ CUtensorMap mapH,
              const __grid_constant__ CUtensorMap mapWiz,
              const __grid_constant__ CUtensorMap mapWir,
              const __grid_constant__ CUtensorMap mapWih,
              const __grid_constant__ CUtensorMap mapWhz,
              const __grid_constant__ CUtensorMap mapWhr,
              const __grid_constant__ CUtensorMap mapWhh,
              const float* __restrict__ h_prev,
              const float* __restrict__ biz, const float* __restrict__ bir,
              const float* __restrict__ big, const float* __restrict__ bhz,
              const float* __restrict__ bhr, const float* __restrict__ bhh,
              float* __restrict__ out)
{
#if HAVE_TCGEN05
    extern __shared__ char smem[];
    const uint32_t sb = smem_u32(smem);
    const int tid = threadIdx.x;
    const uint32_t rank = blockIdx.x & 1;
    // N-fast pair raster (proven)
    const int pair = blockIdx.x >> 1;
    const int colBase  = (pair & 7) * 128;
    const int rowBase  = (pair >> 3) * 256 + (int)rank * 128;
    const int wColBase = colBase + (int)rank * 64;

    if (tid == 0) {
        for (int st = 0; st < NST; st++) {
            MBAR_INIT(sb + OFF_FULL  + st * 8, 1);
            MBAR_INIT(sb + OFF_EMPTY + st * 8, 1);
        }
        MBAR_INIT(sb + OFF_DONE, 1);
    }
    if (tid >= 256) {
        ALLOC_CG2(sb + OFF_TMEM, 512);
    }
    if (tid < 128) {
        int c = colBase + tid;
        float* bb = (float*)(smem + OFF_BIAS);
        bb[tid]       = biz[c] + bhz[c];
        bb[128 + tid] = bir[c] + bhr[c];
        bb[256 + tid] = big[c];
        bb[384 + tid] = bhh[c];
    }
    __syncthreads();
    uint32_t tmem;
    asm volatile("ld.shared.b32 %0, [%1];" : "=r"(tmem) : "r"(sb + OFF_TMEM));
    CLUSTER_SYNC_();   // peer barriers initialized before any cg2 complete_tx

    if (tid == 0) {
        // ---------- producer: single thread per CTA, 4 cg2 TMA loads/stage ---
        int stp = 0, php = 1;    // EMPTY starts "free" (phase 1 trick)
#pragma unroll 1
        for (int chunk = 0; chunk < 64; chunk++) {
            MBAR_WAIT(sb + OFF_EMPTY + stp * 8, php);
            const int k0 = (chunk & 31) * 32;
            const uint32_t stb = sb + SMEM_STAGE0 + stp * STAGE_BYTES;
            const uint32_t mb = sb + OFF_FULL + stp * 8;
            if (rank == 0) MBAR_EXPECT_TX(mb, STAGE_TX2);
            if (chunk < 32) {
                TMA_3D_CG2(stb, &mapX, k0, rowBase, 0, mb);
                TMA_3D_CG2(stb + 16384,         &mapWiz, k0, wColBase, 0, mb);
                TMA_3D_CG2(stb + 16384 + 8192,  &mapWir, k0, wColBase, 0, mb);
                TMA_3D_CG2(stb + 16384 + 16384, &mapWih, k0, wColBase, 0, mb);
            } else {
                TMA_3D_CG2(stb, &mapH, k0, rowBase, 0, mb);
                TMA_3D_CG2(stb + 16384,         &mapWhz, k0, wColBase, 0, mb);
                TMA_3D_CG2(stb + 16384 + 8192,  &mapWhr, k0, wColBase, 0, mb);
                TMA_3D_CG2(stb + 16384 + 16384, &mapWhh, k0, wColBase, 0, mb);
            }
            if (++stp == NST) { stp = 0; php ^= 1; }
        }
    } else if (tid >= 256 && rank == 0) {
        // ---------- control: warp 8 on rank0 — per-stage wait/dispatch/commit
        const int lane = tid - 256;
        int stc = 0, phc = 0;
#pragma unroll 1
        for (int chunk = 0; chunk < 64; chunk++) {
            MBAR_WAIT(sb + OFF_FULL + stc * 8, phc);   // BOTH CTAs' data landed
            if (lane == 0) {
                const uint32_t stb = sb + SMEM_STAGE0 + stc * STAGE_BYTES;
                const uint64_t aD = sdesc(stb);
                const uint32_t tG = (chunk < 32) ? (tmem + 256) : (tmem + 384);
#pragma unroll
                for (int g = 0; g < 3; g++) {
                    const uint64_t bD = sdesc(stb + 16384 + g * 8192);
                    const uint32_t dcol = (g == 0) ? tmem : ((g == 1) ? (tmem + 128) : tG);
#pragma unroll
                    for (int ks = 0; ks < 4; ks++) {
                        uint32_t en = !(ks == 0 && (chunk == 0 || (chunk == 32 && g == 2)));
                        mma_tf32_cg2(dcol, aD + ks * 2, bD + ks * 2, IDESC_TF32, en);
                    }
                }
                COMMIT_MC(sb + OFF_EMPTY + stc * 8);   // frees stage in BOTH CTAs
            }
            if (++stc == NST) { stc = 0; phc ^= 1; }
        }
        if (lane == 0) COMMIT_MC(sb + OFF_DONE);
    }

    // epilogue: warps 0-3 read TMEM, de-bias, fuse activations
    if (tid < 128) {
        MBAR_WAIT(sb + OFF_DONE, 0);
        TC_FENCE_AFTER();
        const int warp = tid >> 5, lane = tid & 31;
        const int grow = rowBase + warp * 32 + lane;
        const float* hrow = h_prev + (size_t)grow * H_DIM + colBase;
        float* orow = out + (size_t)grow * H_DIM + colBase;
        const float* bb = (const float*)(smem + OFF_BIAS);
#pragma unroll 1
        for (int c0 = 0; c0 < 128; c0 += 16) {
            uint32_t rz[16], rr[16], rg[16], rh[16];
            LD_X16(rz, tmem + c0);
            LD_X16(rr, tmem + 128 + c0);
            LD_X16(rg, tmem + 256 + c0);
            LD_X16(rh, tmem + 384 + c0);
            TC_WAIT_LD();
            TC_FENCE_BEFORE();
            float o[16];
#pragma unroll
            for (int j = 0; j < 16; j++) {
                const int cc = c0 + j;
                float az = __uint_as_float(rz[j]) * TRUNC_DEBIAS;
                float ar = __uint_as_float(rr[j]) * TRUNC_DEBIAS;
                float ag = __uint_as_float(rg[j]) * TRUNC_DEBIAS;
                float ah = __uint_as_float(rh[j]) * TRUNC_DEBIAS;
                float z = 1.f / (1.f + __expf(-(az + bb[cc])));
                float r = 1.f / (1.f + __expf(-(ar + bb[128 + cc])));
                float g = tanhf(ag + bb[256 + cc] + r * (ah + bb[384 + cc]));
                o[j] = (1.f - z) * g + z * hrow[cc];
            }
#pragma unroll
            for (int q = 0; q < 4; q++)
                *reinterpret_cast<float4*>(orow + c0 + q * 4) =
                    make_float4(o[q * 4], o[q * 4 + 1], o[q * 4 + 2], o[q * 4 + 3]);
        }
    }

    __syncthreads();
    if (tid >= 256) {
        RELINQ_CG2();
        DEALLOC_CG2(tmem, 512);
    }
    CLUSTER_SYNC_();   // no CTA exits while peer's cg2 TMA/MMA may touch it
#endif // HAVE_TCGEN05
}

// ---------------------------------------------------------------------------
// Launch: 8 tensormaps (driver via dlopen), single kernel launch.
// ---------------------------------------------------------------------------
using TmapEncodeFn = CUresult (*)(
    CUtensorMap*, CUtensorMapDataType, cuuint32_t, void*,
    const cuuint64_t*, const cuuint64_t*, const cuuint32_t*, const cuuint32_t*,
    CUtensorMapInterleave, CUtensorMapSwizzle, CUtensorMapL2promotion,
    CUtensorMapFloatOOBfill);

static void make_map(TmapEncodeFn enc, CUtensorMap* m, const void* ptr,
                     uint64_t rows, uint32_t boxRows) {
    cuuint64_t dims[3]    = {(cuuint64_t)I_DIM, (cuuint64_t)rows, 1};
    cuuint64_t strides[2] = {(cuuint64_t)I_DIM * sizeof(float),
                             (cuuint64_t)rows * I_DIM * sizeof(float)};
    cuuint32_t box[3]     = {32u, boxRows, 1u};   // 32 f32 = 128B = SW128 atom
    cuuint32_t estr[3]    = {1u, 1u, 1u};
    enc(m, CU_TENSOR_MAP_DATA_TYPE_FLOAT32, 3, const_cast<void*>(ptr),
        dims, strides, box, estr,
        CU_TENSOR_MAP_INTERLEAVE_NONE, CU_TENSOR_MAP_SWIZZLE_128B,
        CU_TENSOR_MAP_L2_PROMOTION_L2_128B, CU_TENSOR_MAP_FLOAT_OOB_FILL_NONE);
}

extern "C" void kernel_launch(void* const* d_in, const int* in_sizes, int n_in,
                              void* d_out, int out_size)
{
    const float* x   = (const float*)d_in[0];
    const float* h   = (const float*)d_in[1];
    const float* Wiz = (const float*)d_in[2];
    const float* biz = (const float*)d_in[3];
    const float* Wir = (const float*)d_in[4];
    const float* bir = (const float*)d_in[5];
    const float* Wih = (const float*)d_in[6];
    const float* big = (const float*)d_in[7];
    const float* Whz = (const float*)d_in[8];
    const float* bhz = (const float*)d_in[9];
    const float* Whr = (const float*)d_in[10];
    const float* bhr = (const float*)d_in[11];
    const float* Whh = (const float*)d_in[12];
    const float* bhh = (const float*)d_in[13];
    float* out = (float*)d_out;

    static CUtensorMap mX, mH, mWiz, mWir, mWih, mWhz, mWhr, mWhh;
    {
        void* lib = dlopen("libcuda.so.1", RTLD_NOW | RTLD_GLOBAL);
        TmapEncodeFn enc = lib ? (TmapEncodeFn)dlsym(lib, "cuTensorMapEncodeTiled") : nullptr;
        if (enc) {
            make_map(enc, &mX,   x,   B_DIM, 128);
            make_map(enc, &mH,   h,   B_DIM, 128);
            make_map(enc, &mWiz, Wiz, H_DIM, 64);
            make_map(enc, &mWir, Wir, H_DIM, 64);
            make_map(enc, &mWih, Wih, H_DIM, 64);
            make_map(enc, &mWhz, Whz, H_DIM, 64);
            make_map(enc, &mWhr, Whr, H_DIM, 64);
            make_map(enc, &mWhh, Whh, H_DIM, 64);
        }
    }

    cudaFuncSetAttribute(gru_tc_kernel, cudaFuncAttributeMaxDynamicSharedMemorySize, SMEM_TOTAL_TC);
    dim3 grid(1024, 1);
    gru_tc_kernel<<<grid, 288, SMEM_TOTAL_TC>>>(
        mX, mH, mWiz, mWir, mWih, mWhz, mWhr, mWhh,
        h, biz, bir, big, bhz, bhr, bhh, out);
}